// round 3
// baseline (speedup 1.0000x reference)
#include <cuda_runtime.h>
#include <math.h>

#define LTOK   4096
#define NB     4
#define EDIM   512
#define MSLOT  12
#define DFFDIM 2048
#define NCYC   3
#define SCALE_Q 0.044194173824159216f   // 512^-0.5
#define LNEPS   1e-5f
#define NCOLB  (LTOK/128)               // 32 col-blocks in logits

// ---------------- scratch ----------------
__device__ float g_Kp[NB*LTOK*EDIM];
__device__ float g_Vp[NB*LTOK*EDIM];
__device__ float g_Vf[NB*LTOK*EDIM];
__device__ float g_P[NB*LTOK*LTOK];          // raw gated logits
__device__ float g_Pmax[NB*LTOK*NCOLB];
__device__ float g_Psum[NB*LTOK*NCOLB];
__device__ float g_Rmax[NB*LTOK];
__device__ float g_Rinv[NB*LTOK];
__device__ float g_slots[NB*MSLOT*EDIM];
__device__ float g_Qs[NB*MSLOT*EDIM];
__device__ float g_att[NB*MSLOT*LTOK];
__device__ float g_attsm[NB*MSLOT*LTOK];
__device__ float g_srcn[NB*MSLOT*EDIM];
__device__ float g_h[NB*MSLOT*DFFDIM];
__device__ float g_srcPart[8][NB*MSLOT*EDIM];
__device__ float g_f2p[2][NB*MSLOT*EDIM];

__device__ __forceinline__ unsigned f2tf(float f) {
    unsigned u; asm("cvt.rna.tf32.f32 %0, %1;" : "=r"(u) : "f"(f)); return u;
}

// ================= pipelined tf32 MMA GEMM =================
// block 128x128, k-tile 16, double-buffered smem, 8 warps (2x4), warp 64x32.
// BTRANS=1: B [N][K] (C=A*B^T).  BTRANS=0: B [K][N].
// EPI=1: token_assign gating + online-softmax block partials out.
// SMAX=1: A elements transformed exp(v-rowmax)*rowinv while loading.
template<int BTRANS, int EPI, int SMAX>
__global__ void __launch_bounds__(256, 2)
mma_gemm_kernel(const float* __restrict__ A, int lda, long sAz,
                const float* __restrict__ B, int ldb, long sBz,
                float* __restrict__ C, int ldc, long sCz,
                int K, float scale,
                const float* __restrict__ satt, const float* __restrict__ sassign,
                const float* __restrict__ rowmax, const float* __restrict__ rowinv,
                float* __restrict__ pmax, float* __restrict__ psum)
{
    __shared__ unsigned As[2][128 * 20];
    __shared__ unsigned Bs[2][128 * 20];
    int z = blockIdx.z;
    A += (long)z * sAz; B += (long)z * sBz; C += (long)z * sCz;
    int row0 = blockIdx.y * 128, col0 = blockIdx.x * 128;
    int tid = threadIdx.x, lane = tid & 31, warp = tid >> 5;
    int wm = warp >> 2, wn = warp & 3;
    int gid = lane >> 2, tig = lane & 3;
    int ra = tid >> 2, ka = (tid & 3) << 2;
    float acc[4][4][4] = {};

    float smx[2], sinv[2];
    if (SMAX) {
        #pragma unroll
        for (int i = 0; i < 2; i++) {
            long rr = (long)z * LTOK + row0 + ra + 64 * i;
            smx[i] = rowmax[rr]; sinv[i] = rowinv[rr];
        }
    }

    float4 va[2], vb[2];
    // ---- prologue: load k-tile 0 ----
    #pragma unroll
    for (int i = 0; i < 2; i++)
        va[i] = *(const float4*)&A[(long)(row0 + ra + 64 * i) * lda + ka];
    if (BTRANS) {
        #pragma unroll
        for (int i = 0; i < 2; i++)
            vb[i] = *(const float4*)&B[(long)(col0 + ra + 64 * i) * ldb + ka];
    } else {
        #pragma unroll
        for (int i = 0; i < 2; i++) {
            int idx = tid + 256 * i; int k = idx >> 5, nc = (idx & 31) << 2;
            vb[i] = *(const float4*)&B[(long)k * ldb + col0 + nc];
        }
    }
    #pragma unroll
    for (int i = 0; i < 2; i++) {
        if (SMAX) {
            va[i].x = __expf(va[i].x - smx[i]) * sinv[i];
            va[i].y = __expf(va[i].y - smx[i]) * sinv[i];
            va[i].z = __expf(va[i].z - smx[i]) * sinv[i];
            va[i].w = __expf(va[i].w - smx[i]) * sinv[i];
        }
        uint4 ua = { f2tf(va[i].x), f2tf(va[i].y), f2tf(va[i].z), f2tf(va[i].w) };
        *(uint4*)&As[0][(ra + 64 * i) * 20 + ka] = ua;
        uint4 ub = { f2tf(vb[i].x), f2tf(vb[i].y), f2tf(vb[i].z), f2tf(vb[i].w) };
        if (BTRANS) *(uint4*)&Bs[0][(ra + 64 * i) * 20 + ka] = ub;
        else {
            int idx = tid + 256 * i; int k = idx >> 5, nc = (idx & 31) << 2;
            *(uint4*)&Bs[0][k * 132 + nc] = ub;
        }
    }
    __syncthreads();

    int nbuf = 0;
    for (int kt = 16; kt < K + 16; kt += 16) {
        bool more = kt < K;
        if (more) {
            #pragma unroll
            for (int i = 0; i < 2; i++)
                va[i] = *(const float4*)&A[(long)(row0 + ra + 64 * i) * lda + kt + ka];
            if (BTRANS) {
                #pragma unroll
                for (int i = 0; i < 2; i++)
                    vb[i] = *(const float4*)&B[(long)(col0 + ra + 64 * i) * ldb + kt + ka];
            } else {
                #pragma unroll
                for (int i = 0; i < 2; i++) {
                    int idx = tid + 256 * i; int k = idx >> 5, nc = (idx & 31) << 2;
                    vb[i] = *(const float4*)&B[(long)(kt + k) * ldb + col0 + nc];
                }
            }
        }
        // ---- compute on buffer nbuf ----
        #pragma unroll
        for (int ks = 0; ks < 2; ks++) {
            int k0 = ks * 8;
            unsigned a[4][4], b[4][2];
            #pragma unroll
            for (int mt = 0; mt < 4; mt++) {
                int r = wm * 64 + mt * 16 + gid;
                a[mt][0] = As[nbuf][r * 20 + k0 + tig];
                a[mt][1] = As[nbuf][(r + 8) * 20 + k0 + tig];
                a[mt][2] = As[nbuf][r * 20 + k0 + tig + 4];
                a[mt][3] = As[nbuf][(r + 8) * 20 + k0 + tig + 4];
            }
            #pragma unroll
            for (int nt = 0; nt < 4; nt++) {
                int c = wn * 32 + nt * 8 + gid;
                if (BTRANS) {
                    b[nt][0] = Bs[nbuf][c * 20 + k0 + tig];
                    b[nt][1] = Bs[nbuf][c * 20 + k0 + tig + 4];
                } else {
                    b[nt][0] = Bs[nbuf][(k0 + tig) * 132 + c];
                    b[nt][1] = Bs[nbuf][(k0 + tig + 4) * 132 + c];
                }
            }
            #pragma unroll
            for (int mt = 0; mt < 4; mt++)
                #pragma unroll
                for (int nt = 0; nt < 4; nt++)
                    asm volatile(
                        "mma.sync.aligned.m16n8k8.row.col.f32.tf32.tf32.f32 "
                        "{%0,%1,%2,%3}, {%4,%5,%6,%7}, {%8,%9}, {%0,%1,%2,%3};\n"
                        : "+f"(acc[mt][nt][0]), "+f"(acc[mt][nt][1]),
                          "+f"(acc[mt][nt][2]), "+f"(acc[mt][nt][3])
                        : "r"(a[mt][0]), "r"(a[mt][1]), "r"(a[mt][2]), "r"(a[mt][3]),
                          "r"(b[nt][0]), "r"(b[nt][1]));
        }
        if (more) {
            #pragma unroll
            for (int i = 0; i < 2; i++) {
                if (SMAX) {
                    va[i].x = __expf(va[i].x - smx[i]) * sinv[i];
                    va[i].y = __expf(va[i].y - smx[i]) * sinv[i];
                    va[i].z = __expf(va[i].z - smx[i]) * sinv[i];
                    va[i].w = __expf(va[i].w - smx[i]) * sinv[i];
                }
                uint4 ua = { f2tf(va[i].x), f2tf(va[i].y), f2tf(va[i].z), f2tf(va[i].w) };
                *(uint4*)&As[nbuf ^ 1][(ra + 64 * i) * 20 + ka] = ua;
                uint4 ub = { f2tf(vb[i].x), f2tf(vb[i].y), f2tf(vb[i].z), f2tf(vb[i].w) };
                if (BTRANS) *(uint4*)&Bs[nbuf ^ 1][(ra + 64 * i) * 20 + ka] = ub;
                else {
                    int idx = tid + 256 * i; int k = idx >> 5, nc = (idx & 31) << 2;
                    *(uint4*)&Bs[nbuf ^ 1][k * 132 + nc] = ub;
                }
            }
        }
        __syncthreads();
        nbuf ^= 1;
    }

    // ---------------- epilogue ----------------
    float* Ssa = (float*)As;
    float* Ssg = (float*)As + 1536;
    if (EPI) {
        const float* sa = satt + ((long)z * LTOK + row0) * MSLOT;
        #pragma unroll
        for (int i = 0; i < 6; i++) Ssa[tid + i * 256] = sa[tid + i * 256];
        #pragma unroll
        for (int i = 0; i < 6; i++) {
            int idx = tid + i * 256;
            Ssg[idx] = sassign[((long)z * MSLOT + (idx >> 7)) * LTOK + col0 + (idx & 127)];
        }
        __syncthreads();
        // gate acc in place
        #pragma unroll
        for (int mt = 0; mt < 4; mt++) {
            int r0l = wm * 64 + mt * 16 + gid, r1l = r0l + 8;
            #pragma unroll
            for (int nt = 0; nt < 4; nt++) {
                int c0l = wn * 32 + nt * 8 + 2 * tig;
                float t00 = 0.f, t01 = 0.f, t10 = 0.f, t11 = 0.f;
                #pragma unroll
                for (int m = 0; m < MSLOT; m++) {
                    float sa0 = Ssa[r0l * MSLOT + m], sa1 = Ssa[r1l * MSLOT + m];
                    float sg0 = Ssg[m * 128 + c0l],   sg1 = Ssg[m * 128 + c0l + 1];
                    t00 += sa0 * sg0; t01 += sa0 * sg1;
                    t10 += sa1 * sg0; t11 += sa1 * sg1;
                }
                acc[mt][nt][0] *= t00; acc[mt][nt][1] *= t01;
                acc[mt][nt][2] *= t10; acc[mt][nt][3] *= t11;
            }
        }
    }
    // store C
    #pragma unroll
    for (int mt = 0; mt < 4; mt++) {
        int r0l = wm * 64 + mt * 16 + gid, r1l = r0l + 8;
        #pragma unroll
        for (int nt = 0; nt < 4; nt++) {
            int c0l = wn * 32 + nt * 8 + 2 * tig;
            float s = EPI ? 1.0f : scale;
            float2 o0 = { acc[mt][nt][0] * s, acc[mt][nt][1] * s };
            float2 o1 = { acc[mt][nt][2] * s, acc[mt][nt][3] * s };
            *(float2*)&C[(long)(row0 + r0l) * ldc + col0 + c0l] = o0;
            *(float2*)&C[(long)(row0 + r1l) * ldc + col0 + c0l] = o1;
        }
    }
    if (EPI) {
        // block-partial online softmax stats (per row over this 128-col block)
        float* rmaxS = (float*)Bs;          // [128][4]
        float* rsumS = (float*)Bs + 512;    // [128][4]
        #pragma unroll
        for (int mt = 0; mt < 4; mt++)
            #pragma unroll
            for (int h = 0; h < 2; h++) {
                float mx = -3.4e38f;
                #pragma unroll
                for (int nt = 0; nt < 4; nt++) {
                    mx = fmaxf(mx, acc[mt][nt][2 * h]);
                    mx = fmaxf(mx, acc[mt][nt][2 * h + 1]);
                }
                mx = fmaxf(mx, __shfl_xor_sync(0xffffffffu, mx, 1));
                mx = fmaxf(mx, __shfl_xor_sync(0xffffffffu, mx, 2));
                if (tig == 0) rmaxS[(wm * 64 + mt * 16 + h * 8 + gid) * 4 + wn] = mx;
            }
        __syncthreads();
        #pragma unroll
        for (int mt = 0; mt < 4; mt++)
            #pragma unroll
            for (int h = 0; h < 2; h++) {
                int r = wm * 64 + mt * 16 + h * 8 + gid;
                float M = fmaxf(fmaxf(rmaxS[r * 4], rmaxS[r * 4 + 1]),
                                fmaxf(rmaxS[r * 4 + 2], rmaxS[r * 4 + 3]));
                float s = 0.f;
                #pragma unroll
                for (int nt = 0; nt < 4; nt++)
                    s += __expf(acc[mt][nt][2 * h] - M) + __expf(acc[mt][nt][2 * h + 1] - M);
                s += __shfl_xor_sync(0xffffffffu, s, 1);
                s += __shfl_xor_sync(0xffffffffu, s, 2);
                if (tig == 0) rsumS[r * 4 + wn] = s;
            }
        __syncthreads();
        if (tid < 128) {
            int r = tid;
            float M = fmaxf(fmaxf(rmaxS[r * 4], rmaxS[r * 4 + 1]),
                            fmaxf(rmaxS[r * 4 + 2], rmaxS[r * 4 + 3]));
            float S = rsumS[r * 4] + rsumS[r * 4 + 1] + rsumS[r * 4 + 2] + rsumS[r * 4 + 3];
            long base = ((long)z * LTOK + row0 + r) * NCOLB + blockIdx.x;
            pmax[base] = M; psum[base] = S;
        }
    }
}

// merge 32 block-partials per row -> rowmax, 1/rowsum
__global__ void stats_finish_kernel(const float* __restrict__ pmax, const float* __restrict__ psum,
                                    float* __restrict__ rmax, float* __restrict__ rinv)
{
    int row = blockIdx.x * 4 + (threadIdx.x >> 5);
    int lane = threadIdx.x & 31;
    float M = pmax[(long)row * NCOLB + lane];
    float S = psum[(long)row * NCOLB + lane];
    #pragma unroll
    for (int o = 16; o; o >>= 1) {
        float M2 = __shfl_xor_sync(0xffffffffu, M, o);
        float S2 = __shfl_xor_sync(0xffffffffu, S, o);
        float Mn = fmaxf(M, M2);
        S = S * __expf(M - Mn) + S2 * __expf(M2 - Mn);
        M = Mn;
    }
    if (lane == 0) { rmax[row] = M; rinv[row] = 1.f / S; }
}

// ---------------- batched slot-row GEMM ----------------
// X: [NB*12][K]; all 12 rows of batch n in smem; 256 threads, one out each.
// MODE 0: *scale; 1: +bias, exact gelu; 2: raw partial (K split by blockIdx.z)
template<int MODE>
__global__ void slot_gemm_kernel(const float* __restrict__ X, int K,
                                 const float* __restrict__ W,
                                 const float* __restrict__ bias,
                                 float* __restrict__ Out, int ldo, long partStride,
                                 float scale)
{
    __shared__ float xs[MSLOT * 1024];
    int n = blockIdx.x, tid = threadIdx.x;
    int chunk = (K < 1024) ? K : 1024;
    int base4 = blockIdx.z * 256;           // k offset /4
    int cw = chunk >> 2;
    const float4* X4 = (const float4*)X;
    float4* xs4 = (float4*)xs;
    for (int idx = tid; idx < MSLOT * cw; idx += 256) {
        int m = idx / cw, k4 = idx % cw;
        xs4[m * 256 + k4] = X4[(long)(n * MSLOT + m) * (K >> 2) + base4 + k4];
    }
    __syncthreads();
    int o = blockIdx.y * 256 + tid;
    const float4* w4 = (const float4*)W + (long)o * (K >> 2) + base4;
    float acc[MSLOT] = {};
    for (int k4 = 0; k4 < cw; k4++) {
        float4 w = w4[k4];
        #pragma unroll
        for (int m = 0; m < MSLOT; m++) {
            float4 x = xs4[m * 256 + k4];
            acc[m] += w.x * x.x + w.y * x.y + w.z * x.z + w.w * x.w;
        }
    }
    #pragma unroll
    for (int m = 0; m < MSLOT; m++) {
        float v;
        if (MODE == 0) v = acc[m] * scale;
        else if (MODE == 1) { float t = acc[m] + bias[o]; v = 0.5f * t * (1.0f + erff(t * 0.70710678118654752f)); }
        else v = acc[m];
        long off = (MODE == 2) ? partStride * blockIdx.z : 0;
        Out[off + (long)(n * MSLOT + m) * ldo + o] = v;
    }
}

// ---------------- softmax rows of 4096 (slot attsm only) ----------------
__global__ void softmax_rows_kernel(const float* __restrict__ In, float* __restrict__ Out)
{
    __shared__ float buf[LTOK];
    __shared__ float red[256];
    long base = (long)blockIdx.x * LTOK;
    int tid = threadIdx.x;
    float mx = -3.4e38f;
    for (int i = tid; i < LTOK; i += 256) { float v = In[base + i]; buf[i] = v; mx = fmaxf(mx, v); }
    red[tid] = mx; __syncthreads();
    for (int st = 128; st > 0; st >>= 1) { if (tid < st) red[tid] = fmaxf(red[tid], red[tid + st]); __syncthreads(); }
    mx = red[0]; __syncthreads();
    float s = 0.f;
    for (int i = tid; i < LTOK; i += 256) { float e = expf(buf[i] - mx); buf[i] = e; s += e; }
    red[tid] = s; __syncthreads();
    for (int st = 128; st > 0; st >>= 1) { if (tid < st) red[tid] += red[tid + st]; __syncthreads(); }
    float inv = 1.f / red[0];
    for (int i = tid; i < LTOK; i += 256) Out[base + i] = buf[i] * inv;
}

// ---------------- slot-phase small kernels ----------------
__global__ void init_slots_kernel(const float* __restrict__ sv)
{
    int idx = blockIdx.x * 256 + threadIdx.x;
    if (idx < NB * MSLOT * EDIM) {
        int e = idx % EDIM; int nm = idx / EDIM; int m = nm % MSLOT; int n = nm / MSLOT;
        g_slots[idx] = sv[(m * NB + n) * EDIM + e];
    }
}

__global__ void slots_out_kernel(float* __restrict__ out)
{
    int idx = blockIdx.x * 256 + threadIdx.x;
    if (idx < NB * MSLOT * EDIM) {
        int e = idx % EDIM; int nm = idx / EDIM; int m = nm % MSLOT; int n = nm / MSLOT;
        out[(m * NB + n) * EDIM + e] = g_slots[idx];
    }
}

__global__ void slot_att_kernel()
{
    int n = blockIdx.x;
    int l = blockIdx.y * 128 + threadIdx.x;
    __shared__ float Qsm[MSLOT * EDIM];
    const float* src = g_Qs + n * MSLOT * EDIM;
    for (int i = threadIdx.x; i < MSLOT * EDIM; i += 128) Qsm[i] = src[i];
    __syncthreads();
    const float4* kr = (const float4*)(g_Kp + (long)(l * NB + n) * EDIM);
    float acc[MSLOT] = {};
    for (int e4 = 0; e4 < EDIM / 4; e4++) {
        float4 kv = kr[e4];
        #pragma unroll
        for (int m = 0; m < MSLOT; m++) {
            float4 q = *(const float4*)&Qsm[m * EDIM + e4 * 4];
            acc[m] += q.x * kv.x + q.y * kv.y + q.z * kv.z + q.w * kv.w;
        }
    }
    #pragma unroll
    for (int m = 0; m < MSLOT; m++) g_att[(long)(n * MSLOT + m) * LTOK + l] = acc[m];
}

__global__ void slot_assign_kernel(float* __restrict__ outp)
{
    int n = blockIdx.x;
    int l = blockIdx.y * 256 + threadIdx.x;
    float v[MSLOT]; float mx = -3.4e38f;
    #pragma unroll
    for (int m = 0; m < MSLOT; m++) { v[m] = g_att[(long)(n * MSLOT + m) * LTOK + l]; mx = fmaxf(mx, v[m]); }
    float s = 0.f;
    #pragma unroll
    for (int m = 0; m < MSLOT; m++) { v[m] = expf(v[m] - mx); s += v[m]; }
    float inv = 1.f / s;
    #pragma unroll
    for (int m = 0; m < MSLOT; m++) outp[(long)(n * MSLOT + m) * LTOK + l] = v[m] * inv;
}

// partial attn update: part[z] = attsm(chunk z) @ Vp
__global__ void slot_update_kernel()
{
    int n = blockIdx.x;
    int e = blockIdx.y * 128 + threadIdx.x;
    int z = blockIdx.z;
    __shared__ float w[MSLOT][128];
    float acc[MSLOT] = {};
    for (int l0 = z * 512; l0 < z * 512 + 512; l0 += 128) {
        #pragma unroll
        for (int m = 0; m < MSLOT; m++)
            w[m][threadIdx.x] = g_attsm[(long)(n * MSLOT + m) * LTOK + l0 + threadIdx.x];
        __syncthreads();
        for (int lt = 0; lt < 128; lt++) {
            float v = g_Vp[(long)((l0 + lt) * NB + n) * EDIM + e];
            #pragma unroll
            for (int m = 0; m < MSLOT; m++) acc[m] += w[m][lt] * v;
        }
        __syncthreads();
    }
    #pragma unroll
    for (int m = 0; m < MSLOT; m++)
        g_srcPart[z][(n * MSLOT + m) * EDIM + e] = acc[m];
}

// LN1: x = slots + sum(8 parts) -> LN -> srcn
__global__ void ln1_kernel(const float* __restrict__ gg, const float* __restrict__ bb)
{
    int r = blockIdx.x, tid = threadIdx.x;
    __shared__ float xs[EDIM];
    __shared__ float red[256];
    for (int i = tid; i < EDIM; i += 256) {
        float v = g_slots[r * EDIM + i];
        #pragma unroll
        for (int zz = 0; zz < 8; zz++) v += g_srcPart[zz][r * EDIM + i];
        xs[i] = v;
    }
    __syncthreads();
    float s = 0.f;
    for (int i = tid; i < EDIM; i += 256) s += xs[i];
    red[tid] = s; __syncthreads();
    for (int st = 128; st > 0; st >>= 1) { if (tid < st) red[tid] += red[tid + st]; __syncthreads(); }
    float mean = red[0] / EDIM;
    __syncthreads();
    float sq = 0.f;
    for (int i = tid; i < EDIM; i += 256) { float d = xs[i] - mean; sq += d * d; }
    red[tid] = sq; __syncthreads();
    for (int st = 128; st > 0; st >>= 1) { if (tid < st) red[tid] += red[tid + st]; __syncthreads(); }
    float rstd = rsqrtf(red[0] / EDIM + LNEPS);
    for (int i = tid; i < EDIM; i += 256)
        g_srcn[r * EDIM + i] = (xs[i] - mean) * rstd * gg[i] + bb[i];
}

// LN2: x = srcn + f2p0 + f2p1 + l2_b -> LN -> slots
__global__ void ln2_kernel(const float* __restrict__ l2b,
                           const float* __restrict__ gg, const float* __restrict__ bb)
{
    int r = blockIdx.x, tid = threadIdx.x;
    __shared__ float xs[EDIM];
    __shared__ float red[256];
    for (int i = tid; i < EDIM; i += 256)
        xs[i] = g_srcn[r * EDIM + i] + g_f2p[0][r * EDIM + i] + g_f2p[1][r * EDIM + i] + l2b[i];
    __syncthreads();
    float s = 0.f;
    for (int i = tid; i < EDIM; i += 256) s += xs[i];
    red[tid] = s; __syncthreads();
    for (int st = 128; st > 0; st >>= 1) { if (tid < st) red[tid] += red[tid + st]; __syncthreads(); }
    float mean = red[0] / EDIM;
    __syncthreads();
    float sq = 0.f;
    for (int i = tid; i < EDIM; i += 256) { float d = xs[i] - mean; sq += d * d; }
    red[tid] = sq; __syncthreads();
    for (int st = 128; st > 0; st >>= 1) { if (tid < st) red[tid] += red[tid + st]; __syncthreads(); }
    float rstd = rsqrtf(red[0] / EDIM + LNEPS);
    for (int i = tid; i < EDIM; i += 256)
        g_slots[r * EDIM + i] = (xs[i] - mean) * rstd * gg[i] + bb[i];
}

__global__ void slot_att_final_kernel(const float* __restrict__ Qf, float* __restrict__ outp)
{
    int n = blockIdx.x;
    int l = blockIdx.y * 128 + threadIdx.x;
    __shared__ float S[MSLOT * EDIM];
    const float* sp = g_slots + n * MSLOT * EDIM;
    for (int i = threadIdx.x; i < MSLOT * EDIM; i += 128) S[i] = sp[i];
    __syncthreads();
    const float4* q4 = (const float4*)(Qf + (long)(l * NB + n) * EDIM);
    float acc[MSLOT] = {};
    for (int e4 = 0; e4 < EDIM / 4; e4++) {
        float4 q = q4[e4];
        #pragma unroll
        for (int m = 0; m < MSLOT; m++) {
            float4 sv = *(const float4*)&S[m * EDIM + e4 * 4];
            acc[m] += sv.x * q.x + sv.y * q.y + sv.z * q.z + sv.w * q.w;
        }
    }
    float mx = -3.4e38f;
    #pragma unroll
    for (int m = 0; m < MSLOT; m++) mx = fmaxf(mx, acc[m]);
    float s = 0.f;
    #pragma unroll
    for (int m = 0; m < MSLOT; m++) { acc[m] = expf(acc[m] - mx); s += acc[m]; }
    float inv = 1.f / s;
    #pragma unroll
    for (int m = 0; m < MSLOT; m++) outp[(long)(n * LTOK + l) * MSLOT + m] = acc[m] * inv;
}

// ---------------- host launcher ----------------
extern "C" void kernel_launch(void* const* d_in, const int* in_sizes, int n_in,
                              void* d_out, int out_size)
{
    const float* queries = (const float*)d_in[0];
    const float* keys    = (const float*)d_in[1];
    const float* values  = (const float*)d_in[2];
    const float* slot_v  = (const float*)d_in[3];
    const float* sWq = (const float*)d_in[4];
    const float* sWk = (const float*)d_in[5];
    const float* sWv = (const float*)d_in[6];
    const float* Wq  = (const float*)d_in[7];
    const float* Wk  = (const float*)d_in[8];
    const float* Wv  = (const float*)d_in[9];
    const float* l1_w = (const float*)d_in[10];
    const float* l1_b = (const float*)d_in[11];
    const float* l2_w = (const float*)d_in[12];
    const float* l2_b = (const float*)d_in[13];
    const float* n1_g = (const float*)d_in[14];
    const float* n1_b = (const float*)d_in[15];
    const float* n2_g = (const float*)d_in[16];
    const float* n2_b = (const float*)d_in[17];
    float* out = (float*)d_out;

    float *Kp, *Vp, *Vf, *P, *Pmax, *Psum, *Rmax, *Rinv;
    float *slots, *Qs, *att, *attsm, *srcn, *hbuf, *f2p;
    cudaGetSymbolAddress((void**)&Kp,    g_Kp);
    cudaGetSymbolAddress((void**)&Vp,    g_Vp);
    cudaGetSymbolAddress((void**)&Vf,    g_Vf);
    cudaGetSymbolAddress((void**)&P,     g_P);
    cudaGetSymbolAddress((void**)&Pmax,  g_Pmax);
    cudaGetSymbolAddress((void**)&Psum,  g_Psum);
    cudaGetSymbolAddress((void**)&Rmax,  g_Rmax);
    cudaGetSymbolAddress((void**)&Rinv,  g_Rinv);
    cudaGetSymbolAddress((void**)&slots, g_slots);
    cudaGetSymbolAddress((void**)&Qs,    g_Qs);
    cudaGetSymbolAddress((void**)&att,   g_att);
    cudaGetSymbolAddress((void**)&attsm, g_attsm);
    cudaGetSymbolAddress((void**)&srcn,  g_srcn);
    cudaGetSymbolAddress((void**)&hbuf,  g_h);
    cudaGetSymbolAddress((void**)&f2p,   g_f2p);

    const int o_Q       = LTOK * NB * EDIM;
    const int o_K       = 2 * o_Q;
    const int o_slots   = 3 * o_Q;
    const int o_sassign = o_slots + MSLOT * NB * EDIM;
    const int o_satt    = o_sassign + NB * MSLOT * LTOK;
    const long pstride  = (long)NB * MSLOT * EDIM;

    dim3 gProj(EDIM / 128, (LTOK * NB) / 128, 1);

    mma_gemm_kernel<1,0,0><<<gProj, 256>>>(queries, EDIM, 0, sWk, EDIM, 0, Kp, EDIM, 0,
                                           EDIM, 1.0f, 0, 0, 0, 0, 0, 0);
    mma_gemm_kernel<1,0,0><<<gProj, 256>>>(queries, EDIM, 0, sWv, EDIM, 0, Vp, EDIM, 0,
                                           EDIM, 1.0f, 0, 0, 0, 0, 0, 0);
    init_slots_kernel<<<96, 256>>>(slot_v);

    for (int c = 0; c < NCYC; c++) {
        slot_gemm_kernel<0><<<dim3(NB, EDIM / 256, 1), 256>>>(slots, EDIM, sWq, 0, Qs, EDIM, 0, SCALE_Q);
        slot_att_kernel<<<dim3(NB, LTOK / 128), 128>>>();
        softmax_rows_kernel<<<NB * MSLOT, 256>>>(att, attsm);
        if (c == NCYC - 1)
            slot_assign_kernel<<<dim3(NB, LTOK / 256), 256>>>(out + o_sassign);
        slot_update_kernel<<<dim3(NB, EDIM / 128, 8), 128>>>();
        ln1_kernel<<<NB * MSLOT, 256>>>(n1_g, n1_b);
        slot_gemm_kernel<1><<<dim3(NB, DFFDIM / 256, 1), 256>>>(srcn, EDIM, l1_w, l1_b, hbuf, DFFDIM, 0, 1.0f);
        slot_gemm_kernel<2><<<dim3(NB, EDIM / 256, 2), 256>>>(hbuf, DFFDIM, l2_w, 0, f2p, EDIM, pstride, 1.0f);
        ln2_kernel<<<NB * MSLOT, 256>>>(l2_b, n2_g, n2_b);
    }

    slots_out_kernel<<<96, 256>>>(out + o_slots);

    mma_gemm_kernel<1,0,0><<<gProj, 256>>>(queries, EDIM, 0, Wq, EDIM, 0, out + o_Q, EDIM, 0,
                                           EDIM, SCALE_Q, 0, 0, 0, 0, 0, 0);
    mma_gemm_kernel<1,0,0><<<gProj, 256>>>(keys,    EDIM, 0, Wk, EDIM, 0, out + o_K, EDIM, 0,
                                           EDIM, 1.0f, 0, 0, 0, 0, 0, 0);
    mma_gemm_kernel<1,0,0><<<gProj, 256>>>(values,  EDIM, 0, Wv, EDIM, 0, Vf,        EDIM, 0,
                                           EDIM, 1.0f, 0, 0, 0, 0, 0, 0);

    slot_att_final_kernel<<<dim3(NB, LTOK / 128), 128>>>(out + o_Q, out + o_satt);

    // logits (gated) + block softmax partials
    mma_gemm_kernel<1,1,0><<<dim3(NCOLB, LTOK / 128, NB), 256>>>(
        out + o_Q, NB * EDIM, EDIM,
        out + o_K, NB * EDIM, EDIM,
        P, LTOK, (long)LTOK * LTOK,
        EDIM, 1.0f, out + o_satt, out + o_sassign, 0, 0, Pmax, Psum);
    stats_finish_kernel<<<NB * LTOK / 4, 128>>>(Pmax, Psum, Rmax, Rinv);
    // out = softmax(P) @ Vf with on-the-fly exp-normalize
    mma_gemm_kernel<0,0,1><<<dim3(EDIM / 128, LTOK / 128, NB), 256>>>(
        P, LTOK, (long)LTOK * LTOK,
        Vf, NB * EDIM, EDIM,
        out, NB * EDIM, EDIM,
        LTOK, 1.0f, 0, 0, Rmax, Rinv, 0, 0);
}